// round 6
// baseline (speedup 1.0000x reference)
#include <cuda_runtime.h>
#include <math.h>

// Lloyd-Max LUT restricted to the nonnegative half: x_unit = (x - min)/scale >= 0,
// so searchsorted over all 15 boundaries reduces to 7 + #{j in 7..14 : b_j < xu}.
// c[0..8] = centroids 7..15, b[0..7] = boundaries 7..14 (f32, bit-matching the
// reference: f64 Lloyd-Max -> f32 centroids -> f32 midpoints). b[0] ~ +4e-5 > 0:
// the x=0 grid point (heaviest pdf weight) sits in the NEGATIVE inner bin under
// searchsorted-left, pulling c7 up. xu==0 (the group-min element) -> c[0] = c7.
struct QLut {
    float c[9];
    float b[8];
};

__device__ __forceinline__ float quant_lookup(float xu, const QLut& lut) {
    float r = lut.c[0];
#pragma unroll
    for (int j = 0; j < 8; j++) {
        r = (xu > lut.b[j]) ? lut.c[j + 1] : r;   // FSETP + FSEL, cbank operands
    }
    return r;
}

// Unfused product + left-to-right add: mirrors the reference's elementwise
// multiply (rounded) followed by sum. No FMA contraction on device.
__device__ __forceinline__ float dot4_unfused(float a0, float b0, float a1, float b1,
                                              float a2, float b2, float a3, float b3) {
    float p0 = __fmul_rn(a0, b0);
    float p1 = __fmul_rn(a1, b1);
    float p2 = __fmul_rn(a2, b2);
    float p3 = __fmul_rn(a3, b3);
    return __fadd_rn(__fadd_rn(__fadd_rn(p0, p1), p2), p3);
}

__global__ void __launch_bounds__(256)
turboquant_kernel(const float4* __restrict__ in, float4* __restrict__ out,
                  int nrows, QLut lut) {
    int row  = (blockIdx.x << 3) + (threadIdx.x >> 5);   // 8 rows (warps) per block
    if (row >= nrows) return;                             // warp-uniform (never taken)
    int lane = threadIdx.x & 31;
    size_t idx = (size_t)row * 32 + lane;                 // float4 index; 512B/row coalesced

    float4 v = __ldg(in + idx);
    float x0 = v.x, x1 = v.y, x2 = v.z, x3 = v.w;

    // ---- v_min over the row (exact; min is order-independent) ----
    float mn = fminf(fminf(x0, x1), fminf(x2, x3));
#pragma unroll
    for (int s = 16; s > 0; s >>= 1)
        mn = fminf(mn, __shfl_xor_sync(0xffffffffu, mn, s));

    // ---- centered + sum of squares ----
    float c0 = __fadd_rn(x0, -mn), c1 = __fadd_rn(x1, -mn);
    float c2 = __fadd_rn(x2, -mn), c3 = __fadd_rn(x3, -mn);
    float ss = dot4_unfused(c0, c0, c1, c1, c2, c2, c3, c3);
#pragma unroll
    for (int s = 16; s > 0; s >>= 1)
        ss = __fadd_rn(ss, __shfl_xor_sync(0xffffffffu, ss, s));

    // v_scale = ||centered|| / sqrt(128); IEEE sqrt + IEEE div
    float vs    = __fdiv_rn(__fsqrt_rn(ss), 11.313708498984761f);
    float denom = __fadd_rn(vs, 1e-10f);

    // ---- x_unit via per-element IEEE division (matches reference op exactly) ----
    float r0 = quant_lookup(__fdiv_rn(c0, denom), lut);
    float r1 = quant_lookup(__fdiv_rn(c1, denom), lut);
    float r2 = quant_lookup(__fdiv_rn(c2, denom), lut);
    float r3 = quant_lookup(__fdiv_rn(c3, denom), lut);

    // ---- refined gamma: least-squares fit ----
    float num = dot4_unfused(c0, r0, c1, r1, c2, r2, c3, r3);
    float den = dot4_unfused(r0, r0, r1, r1, r2, r2, r3, r3);
#pragma unroll
    for (int s = 16; s > 0; s >>= 1) {
        num = __fadd_rn(num, __shfl_xor_sync(0xffffffffu, num, s));
        den = __fadd_rn(den, __shfl_xor_sync(0xffffffffu, den, s));
    }
    float g = __fdiv_rn(num, __fadd_rn(den, 1e-10f));

    float4 o;
    o.x = __fadd_rn(__fmul_rn(r0, g), mn);
    o.y = __fadd_rn(__fmul_rn(r1, g), mn);
    o.z = __fadd_rn(__fmul_rn(r2, g), mn);
    o.w = __fadd_rn(__fmul_rn(r3, g), mn);
    out[idx] = o;
}

// ---------------------------------------------------------------------------
// Host: bit-faithful replication of the reference's discrete Lloyd-Max.
// CRITICAL: gcc defaults to -ffp-contract=fast on host code; the linspace
// expression j*delta + (-10.0) must NOT be fused into an FMA, or the grid
// midpoint becomes +4.79e-16 instead of exactly 0.0 and the heaviest pdf
// point (x=0) lands in the wrong bin every iteration, shifting the inner
// centroids by ~9e-5 and flipping the middle boundary's sign. volatile
// temporaries force numpy's separate-rounding semantics. Same treatment for
// the pdf*x accumulation (numpy rounds the product array before bincount).
// Runs at capture time only; no device memory.
// ---------------------------------------------------------------------------
static void lloyd_laplace_centroids(float cf[16]) {
    static double xs[200001];
    static double pdf[200001];
    const int NX = 200001;
    const double delta = 20.0 / 200000.0;
    for (int j = 0; j < NX; j++) {
        volatile double prod = (double)j * delta;   // round the product first
        xs[j] = prod + (-10.0);                     // then round the add (no FMA)
    }
    xs[NX - 1] = 10.0;                              // numpy linspace endpoint
    for (int j = 0; j < NX; j++) pdf[j] = 0.5 * exp(-fabs(xs[j]));

    double c[16];
    for (int i = 0; i < 16; i++) {
        double p = ((double)i + 0.5) / 16.0;
        c[i] = (p < 0.5) ? log(2.0 * p) : -log(2.0 * (1.0 - p));
    }

    for (int it = 0; it < 200; it++) {
        double b[15];
        for (int i = 0; i < 15; i++) b[i] = 0.5 * (c[i + 1] + c[i]);
        double w[16], xw[16];
        for (int i = 0; i < 16; i++) { w[i] = 0.0; xw[i] = 0.0; }
        int bin = 0;  // xs ascending, boundaries ascending -> monotone advance
        for (int j = 0; j < NX; j++) {
            double x = xs[j];
            while (bin < 15 && b[bin] < x) bin++;   // searchsorted 'left'
            w[bin] += pdf[j];
            volatile double px = pdf[j] * x;        // round product (no FMA fuse)
            xw[bin] += px;
        }
        for (int i = 0; i < 16; i++) {
            if (w[i] > 0.0) c[i] = xw[i] / (w[i] > 1e-30 ? w[i] : 1e-30);
        }
    }
    for (int i = 0; i < 16; i++) cf[i] = (float)c[i];
}

extern "C" void kernel_launch(void* const* d_in, const int* in_sizes, int n_in,
                              void* d_out, int out_size) {
    (void)n_in; (void)out_size;
    const float4* in  = (const float4*)d_in[0];
    float4*       out = (float4*)d_out;

    int n     = in_sizes[0];
    int nrows = n / 128;

    // Deterministic recompute every call (no caching per harness rules).
    float cf[16];
    lloyd_laplace_centroids(cf);
    // Boundaries in f32 exactly as the reference: 0.5f * (c[i+1] + c[i])
    float bf[15];
    for (int i = 0; i < 15; i++) bf[i] = 0.5f * (cf[i + 1] + cf[i]);

    QLut lut;
    for (int k = 0; k < 9; k++) lut.c[k] = cf[7 + k];
    for (int k = 0; k < 8; k++) lut.b[k] = bf[7 + k];   // b[0] = b7f ~ +4e-5 > 0

    int blocks = (nrows + 7) / 8;
    turboquant_kernel<<<blocks, 256>>>(in, out, nrows, lut);
}

// round 7
// speedup vs baseline: 1.3490x; 1.3490x over previous
#include <cuda_runtime.h>
#include <math.h>

// Lloyd-Max LUT restricted to the nonnegative half: x_unit = (x - min)/scale >= 0,
// so searchsorted over all 15 boundaries reduces to 7 + #{j in 7..14 : b_j < xu}.
// c[0..8] = centroids 7..15, b[0..7] = boundaries 7..14 (f32, bit-matching the
// reference via the FMA-free host Lloyd-Max below). b[0] ~ +4e-5 > 0.
// xu==0 (the group-min element) -> c[0] = c7.
struct QLut {
    float c[9];
    float b[8];
};

__device__ __forceinline__ float quant_lookup(float xu, const QLut& lut) {
    float r = lut.c[0];
#pragma unroll
    for (int j = 0; j < 8; j++) {
        r = (xu > lut.b[j]) ? lut.c[j + 1] : r;   // FSETP + FSEL, cbank operands
    }
    return r;
}

__global__ void __launch_bounds__(256)
turboquant_kernel(const float4* __restrict__ in, float4* __restrict__ out,
                  int nrows, QLut lut) {
    int row  = (blockIdx.x << 3) + (threadIdx.x >> 5);   // 8 rows (warps) per block
    if (row >= nrows) return;                             // warp-uniform (never taken)
    int lane = threadIdx.x & 31;
    size_t idx = (size_t)row * 32 + lane;                 // float4 index; 512B/row coalesced

    float4 v = __ldg(in + idx);
    float x0 = v.x, x1 = v.y, x2 = v.z, x3 = v.w;

    // ---- v_min over the row (exact; min is order-independent) ----
    float mn = fminf(fminf(x0, x1), fminf(x2, x3));
#pragma unroll
    for (int s = 16; s > 0; s >>= 1)
        mn = fminf(mn, __shfl_xor_sync(0xffffffffu, mn, s));

    // ---- centered + sum of squares (FMA; measured error contribution ~1.4e-4) ----
    float c0 = x0 - mn, c1 = x1 - mn, c2 = x2 - mn, c3 = x3 - mn;
    float ss = fmaf(c0, c0, fmaf(c1, c1, fmaf(c2, c2, c3 * c3)));
#pragma unroll
    for (int s = 16; s > 0; s >>= 1)
        ss += __shfl_xor_sync(0xffffffffu, ss, s);

    // v_scale = ||centered|| / sqrt(128); one fast reciprocal, then multiplies
    float vs  = __fsqrt_rn(ss) * 0.08838834764831845f;   // 1/sqrt(128)
    float inv = __fdividef(1.0f, vs + 1e-10f);

    // ---- LUT quantize (unit reconstruction) ----
    float r0 = quant_lookup(c0 * inv, lut);
    float r1 = quant_lookup(c1 * inv, lut);
    float r2 = quant_lookup(c2 * inv, lut);
    float r3 = quant_lookup(c3 * inv, lut);

    // ---- refined gamma: least-squares fit ----
    float num = fmaf(c0, r0, fmaf(c1, r1, fmaf(c2, r2, c3 * r3)));
    float den = fmaf(r0, r0, fmaf(r1, r1, fmaf(r2, r2, r3 * r3)));
#pragma unroll
    for (int s = 16; s > 0; s >>= 1) {
        num += __shfl_xor_sync(0xffffffffu, num, s);
        den += __shfl_xor_sync(0xffffffffu, den, s);
    }
    float g = __fdividef(num, den + 1e-10f);

    float4 o;
    o.x = fmaf(r0, g, mn);
    o.y = fmaf(r1, g, mn);
    o.z = fmaf(r2, g, mn);
    o.w = fmaf(r3, g, mn);
    out[idx] = o;
}

// ---------------------------------------------------------------------------
// Host: bit-faithful replication of the reference's discrete Lloyd-Max.
// CRITICAL: gcc defaults to fp-contract on host code; the linspace expression
// j*delta + (-10.0) must NOT fuse into an FMA, or the grid midpoint becomes
// +4.79e-16 instead of exactly 0.0 and the heaviest pdf point (x=0) lands in
// the wrong bin, shifting the inner centroids ~9e-5 and flipping the middle
// boundary's sign (this was the R2-R5 0.082/0.018 failure). volatile
// temporaries force numpy's separate-rounding semantics; same for pdf*x.
// Runs at capture time only; no device memory.
// ---------------------------------------------------------------------------
static void lloyd_laplace_centroids(float cf[16]) {
    static double xs[200001];
    static double pdf[200001];
    const int NX = 200001;
    const double delta = 20.0 / 200000.0;
    for (int j = 0; j < NX; j++) {
        volatile double prod = (double)j * delta;   // round the product first
        xs[j] = prod + (-10.0);                     // then round the add (no FMA)
    }
    xs[NX - 1] = 10.0;                              // numpy linspace endpoint
    for (int j = 0; j < NX; j++) pdf[j] = 0.5 * exp(-fabs(xs[j]));

    double c[16];
    for (int i = 0; i < 16; i++) {
        double p = ((double)i + 0.5) / 16.0;
        c[i] = (p < 0.5) ? log(2.0 * p) : -log(2.0 * (1.0 - p));
    }

    for (int it = 0; it < 200; it++) {
        double b[15];
        for (int i = 0; i < 15; i++) b[i] = 0.5 * (c[i + 1] + c[i]);
        double w[16], xw[16];
        for (int i = 0; i < 16; i++) { w[i] = 0.0; xw[i] = 0.0; }
        int bin = 0;  // xs ascending, boundaries ascending -> monotone advance
        for (int j = 0; j < NX; j++) {
            double x = xs[j];
            while (bin < 15 && b[bin] < x) bin++;   // searchsorted 'left'
            w[bin] += pdf[j];
            volatile double px = pdf[j] * x;        // round product (no FMA fuse)
            xw[bin] += px;
        }
        for (int i = 0; i < 16; i++) {
            if (w[i] > 0.0) c[i] = xw[i] / (w[i] > 1e-30 ? w[i] : 1e-30);
        }
    }
    for (int i = 0; i < 16; i++) cf[i] = (float)c[i];
}

extern "C" void kernel_launch(void* const* d_in, const int* in_sizes, int n_in,
                              void* d_out, int out_size) {
    (void)n_in; (void)out_size;
    const float4* in  = (const float4*)d_in[0];
    float4*       out = (float4*)d_out;

    int n     = in_sizes[0];
    int nrows = n / 128;

    // Deterministic recompute every call (no caching per harness rules).
    float cf[16];
    lloyd_laplace_centroids(cf);
    // Boundaries in f32 exactly as the reference: 0.5f * (c[i+1] + c[i])
    float bf[15];
    for (int i = 0; i < 15; i++) bf[i] = 0.5f * (cf[i + 1] + cf[i]);

    QLut lut;
    for (int k = 0; k < 9; k++) lut.c[k] = cf[7 + k];
    for (int k = 0; k < 8; k++) lut.b[k] = bf[7 + k];   // b[0] = b7f ~ +4e-5 > 0

    int blocks = (nrows + 7) / 8;
    turboquant_kernel<<<blocks, 256>>>(in, out, nrows, lut);
}

// round 8
// speedup vs baseline: 1.5561x; 1.1535x over previous
#include <cuda_runtime.h>
#include <math.h>

// Lloyd-Max LUT restricted to the nonnegative half: x_unit = (x - min)/scale >= 0,
// so searchsorted over all 15 boundaries reduces to 7 + #{j in 7..14 : b_j < xu}.
// c[0..8] = centroids 7..15, b[0..7] = boundaries 7..14 (f32, bit-matching the
// reference via the FMA-free host Lloyd-Max below). b[0] ~ +4e-5 > 0.
// xu==0 (the group-min element) -> c[0] = c7.
struct QLut {
    float c[9];
    float b[8];
};

__device__ __forceinline__ float quant_lookup(float xu, const QLut& lut) {
    float r = lut.c[0];
#pragma unroll
    for (int j = 0; j < 8; j++) {
        r = (xu > lut.b[j]) ? lut.c[j + 1] : r;   // FSETP + FSEL, cbank operands
    }
    return r;
}

// 16 lanes per row, 8 elements per lane. shfl_xor with s in {8,4,2,1} stays
// within each 16-lane half-warp, so two rows reduce independently in one warp.
__global__ void __launch_bounds__(256)
turboquant_kernel(const float4* __restrict__ in, float4* __restrict__ out,
                  int nrows, QLut lut) {
    int tid    = threadIdx.x;
    int lane16 = tid & 15;
    int row    = (blockIdx.x << 4) + (tid >> 4);         // 16 rows per block
    if (row >= nrows) return;                             // warp-uniform (never taken)
    size_t base = (size_t)row * 32 + lane16;              // float4 units; row = 32 float4

    float4 va = in[base];                                 // fully coalesced 128B lines
    float4 vb = in[base + 16];

    // ---- thread-local min / sum / sum-of-squares over 8 elems ----
    float mn = fminf(fminf(fminf(va.x, va.y), fminf(va.z, va.w)),
                     fminf(fminf(vb.x, vb.y), fminf(vb.z, vb.w)));
    float sx = ((va.x + va.y) + (va.z + va.w)) + ((vb.x + vb.y) + (vb.z + vb.w));
    float sxx = fmaf(va.x, va.x, fmaf(va.y, va.y, fmaf(va.z, va.z, fmaf(va.w, va.w,
                fmaf(vb.x, vb.x, fmaf(vb.y, vb.y, fmaf(vb.z, vb.z, vb.w * vb.w)))))));

    // ---- one fused 4-stage butterfly for (min, sx, sxx) ----
#pragma unroll
    for (int s = 8; s > 0; s >>= 1) {
        mn  = fminf(mn, __shfl_xor_sync(0xffffffffu, mn, s));
        sx  += __shfl_xor_sync(0xffffffffu, sx, s);
        sxx += __shfl_xor_sync(0xffffffffu, sxx, s);
    }

    // ss = sum((x-mn)^2) = sxx - 2*mn*sx + 128*mn^2 (closed form; no cancellation:
    // terms ~{128, +-60, 933} vs result ~1000; extra noise ~6e-8 rel)
    float ss  = fmaf(mn, fmaf(128.0f, mn, -2.0f * sx), sxx);
    float vs  = __fsqrt_rn(ss) * 0.08838834764831845f;    // /sqrt(128)
    float inv = __fdividef(1.0f, vs + 1e-10f);

    // ---- centered + LUT quantize ----
    float c0 = va.x - mn, c1 = va.y - mn, c2 = va.z - mn, c3 = va.w - mn;
    float c4 = vb.x - mn, c5 = vb.y - mn, c6 = vb.z - mn, c7 = vb.w - mn;

    float r0 = quant_lookup(c0 * inv, lut);
    float r1 = quant_lookup(c1 * inv, lut);
    float r2 = quant_lookup(c2 * inv, lut);
    float r3 = quant_lookup(c3 * inv, lut);
    float r4 = quant_lookup(c4 * inv, lut);
    float r5 = quant_lookup(c5 * inv, lut);
    float r6 = quant_lookup(c6 * inv, lut);
    float r7 = quant_lookup(c7 * inv, lut);

    // ---- refined gamma: least-squares fit ----
    float num = fmaf(c0, r0, fmaf(c1, r1, fmaf(c2, r2, fmaf(c3, r3,
                fmaf(c4, r4, fmaf(c5, r5, fmaf(c6, r6, c7 * r7)))))));
    float den = fmaf(r0, r0, fmaf(r1, r1, fmaf(r2, r2, fmaf(r3, r3,
                fmaf(r4, r4, fmaf(r5, r5, fmaf(r6, r6, r7 * r7)))))));
#pragma unroll
    for (int s = 8; s > 0; s >>= 1) {
        num += __shfl_xor_sync(0xffffffffu, num, s);
        den += __shfl_xor_sync(0xffffffffu, den, s);
    }
    float g = __fdividef(num, den + 1e-10f);

    float4 oa, ob;
    oa.x = fmaf(r0, g, mn); oa.y = fmaf(r1, g, mn);
    oa.z = fmaf(r2, g, mn); oa.w = fmaf(r3, g, mn);
    ob.x = fmaf(r4, g, mn); ob.y = fmaf(r5, g, mn);
    ob.z = fmaf(r6, g, mn); ob.w = fmaf(r7, g, mn);
    out[base]      = oa;
    out[base + 16] = ob;
}

// ---------------------------------------------------------------------------
// Host: bit-faithful replication of the reference's discrete Lloyd-Max.
// CRITICAL: the linspace expression j*delta + (-10.0) must NOT fuse into an
// FMA (volatile breaks contraction), or the grid midpoint becomes +4.79e-16
// instead of exactly 0.0, the heaviest pdf point lands in the wrong bin, and
// the inner centroids shift ~9e-5 flipping the middle boundary's sign
// (the R2-R5 0.082/0.018 failures). Same for pdf*x. Capture-time only.
// ---------------------------------------------------------------------------
static void lloyd_laplace_centroids(float cf[16]) {
    static double xs[200001];
    static double pdf[200001];
    const int NX = 200001;
    const double delta = 20.0 / 200000.0;
    for (int j = 0; j < NX; j++) {
        volatile double prod = (double)j * delta;   // round the product first
        xs[j] = prod + (-10.0);                     // then round the add (no FMA)
    }
    xs[NX - 1] = 10.0;                              // numpy linspace endpoint
    for (int j = 0; j < NX; j++) pdf[j] = 0.5 * exp(-fabs(xs[j]));

    double c[16];
    for (int i = 0; i < 16; i++) {
        double p = ((double)i + 0.5) / 16.0;
        c[i] = (p < 0.5) ? log(2.0 * p) : -log(2.0 * (1.0 - p));
    }

    for (int it = 0; it < 200; it++) {
        double b[15];
        for (int i = 0; i < 15; i++) b[i] = 0.5 * (c[i + 1] + c[i]);
        double w[16], xw[16];
        for (int i = 0; i < 16; i++) { w[i] = 0.0; xw[i] = 0.0; }
        int bin = 0;  // xs ascending, boundaries ascending -> monotone advance
        for (int j = 0; j < NX; j++) {
            double x = xs[j];
            while (bin < 15 && b[bin] < x) bin++;   // searchsorted 'left'
            w[bin] += pdf[j];
            volatile double px = pdf[j] * x;        // round product (no FMA fuse)
            xw[bin] += px;
        }
        for (int i = 0; i < 16; i++) {
            if (w[i] > 0.0) c[i] = xw[i] / (w[i] > 1e-30 ? w[i] : 1e-30);
        }
    }
    for (int i = 0; i < 16; i++) cf[i] = (float)c[i];
}

extern "C" void kernel_launch(void* const* d_in, const int* in_sizes, int n_in,
                              void* d_out, int out_size) {
    (void)n_in; (void)out_size;
    const float4* in  = (const float4*)d_in[0];
    float4*       out = (float4*)d_out;

    int n     = in_sizes[0];
    int nrows = n / 128;

    // Deterministic recompute every call (no caching per harness rules).
    float cf[16];
    lloyd_laplace_centroids(cf);
    // Boundaries in f32 exactly as the reference: 0.5f * (c[i+1] + c[i])
    float bf[15];
    for (int i = 0; i < 15; i++) bf[i] = 0.5f * (cf[i + 1] + cf[i]);

    QLut lut;
    for (int k = 0; k < 9; k++) lut.c[k] = cf[7 + k];
    for (int k = 0; k < 8; k++) lut.b[k] = bf[7 + k];   // b[0] = b7f ~ +4e-5 > 0

    int blocks = (nrows + 15) / 16;                     // 16 rows per block
    turboquant_kernel<<<blocks, 256>>>(in, out, nrows, lut);
}

// round 9
// speedup vs baseline: 1.6450x; 1.0571x over previous
#include <cuda_runtime.h>
#include <math.h>

// Lloyd-Max LUT restricted to the nonnegative half: x_unit = (x - min)/scale >= 0,
// so searchsorted over all 15 boundaries reduces to 7 + #{j in 7..14 : b_j < xu}.
// c[0..8] = centroids 7..15, b[0..7] = boundaries 7..14 (f32, bit-matching the
// reference via the FMA-free host Lloyd-Max below). b[0] ~ +4e-5 > 0.
// xu==0 (the group-min element) -> c[0] = c7.
//
// Pipe balance: boundaries 0..5 via FSETP/FSEL (ALU pipe); boundaries 6..7 via
// exact saturating-FMA indicators (FMA pipe): with BIG = 2^100 (power of two),
// b*BIG is exact, so sat(fma(xu, BIG, -b*BIG)) == (xu > b) ? 1.0f : 0.0f exactly.
struct QLut {
    float c[7];      // centroids 7..13 (chain part ends at c[6] = centroid 13)
    float b[6];      // boundaries 7..12 (compare part)
    float nb6, nb7;  // -b13*2^100, -b14*2^100 (exact)
    float d6, d7;    // c14-c13, c15-c14
};

#define BIG_F (0x1p100f)

__device__ __forceinline__ float sat_step(float xu, float negbBig) {
    float s;
    asm("fma.rn.sat.f32 %0, %1, %2, %3;" : "=f"(s) : "f"(xu), "f"(BIG_F), "f"(negbBig));
    return s;   // exactly 1.0f if xu > b, else 0.0f
}

__device__ __forceinline__ float quant_lookup(float xu, const QLut& lut) {
    float r = lut.c[0];
#pragma unroll
    for (int j = 0; j < 6; j++) {
        r = (xu > lut.b[j]) ? lut.c[j + 1] : r;   // ALU: FSETP + FSEL
    }
    float s6 = sat_step(xu, lut.nb6);             // FMA pipe
    float s7 = sat_step(xu, lut.nb7);
    r = fmaf(s6, lut.d6, r);
    r = fmaf(s7, lut.d7, r);
    return r;
}

// 16 lanes per row, 8 elements per lane. shfl_xor with s in {8,4,2,1} stays
// within each 16-lane half-warp, so two rows reduce independently in one warp.
__global__ void __launch_bounds__(256)
turboquant_kernel(const float4* __restrict__ in, float4* __restrict__ out,
                  int nrows, QLut lut) {
    int tid    = threadIdx.x;
    int lane16 = tid & 15;
    int row    = (blockIdx.x << 4) + (tid >> 4);         // 16 rows per block
    if (row >= nrows) return;                             // warp-uniform (never taken)
    size_t base = (size_t)row * 32 + lane16;              // float4 units; row = 32 float4

    float4 va = in[base];                                 // fully coalesced 128B lines
    float4 vb = in[base + 16];

    // ---- thread-local min / sum / sum-of-squares over 8 elems ----
    float mn = fminf(fminf(fminf(va.x, va.y), fminf(va.z, va.w)),
                     fminf(fminf(vb.x, vb.y), fminf(vb.z, vb.w)));
    float sx = ((va.x + va.y) + (va.z + va.w)) + ((vb.x + vb.y) + (vb.z + vb.w));
    float sxx = fmaf(va.x, va.x, fmaf(va.y, va.y, fmaf(va.z, va.z, fmaf(va.w, va.w,
                fmaf(vb.x, vb.x, fmaf(vb.y, vb.y, fmaf(vb.z, vb.z, vb.w * vb.w)))))));

    // ---- one fused 4-stage butterfly for (min, sx, sxx) ----
#pragma unroll
    for (int s = 8; s > 0; s >>= 1) {
        mn  = fminf(mn, __shfl_xor_sync(0xffffffffu, mn, s));
        sx  += __shfl_xor_sync(0xffffffffu, sx, s);
        sxx += __shfl_xor_sync(0xffffffffu, sxx, s);
    }

    // ss = sum((x-mn)^2) = sxx - 2*mn*sx + 128*mn^2 (closed form; no cancellation)
    float ss  = fmaf(mn, fmaf(128.0f, mn, -2.0f * sx), sxx);
    float vs  = __fsqrt_rn(ss) * 0.08838834764831845f;    // /sqrt(128)
    float inv = __fdividef(1.0f, vs + 1e-10f);

    // ---- centered + LUT quantize ----
    float c0 = va.x - mn, c1 = va.y - mn, c2 = va.z - mn, c3 = va.w - mn;
    float c4 = vb.x - mn, c5 = vb.y - mn, c6 = vb.z - mn, c7 = vb.w - mn;

    float r0 = quant_lookup(c0 * inv, lut);
    float r1 = quant_lookup(c1 * inv, lut);
    float r2 = quant_lookup(c2 * inv, lut);
    float r3 = quant_lookup(c3 * inv, lut);
    float r4 = quant_lookup(c4 * inv, lut);
    float r5 = quant_lookup(c5 * inv, lut);
    float r6 = quant_lookup(c6 * inv, lut);
    float r7 = quant_lookup(c7 * inv, lut);

    // ---- refined gamma: least-squares fit ----
    float num = fmaf(c0, r0, fmaf(c1, r1, fmaf(c2, r2, fmaf(c3, r3,
                fmaf(c4, r4, fmaf(c5, r5, fmaf(c6, r6, c7 * r7)))))));
    float den = fmaf(r0, r0, fmaf(r1, r1, fmaf(r2, r2, fmaf(r3, r3,
                fmaf(r4, r4, fmaf(r5, r5, fmaf(r6, r6, r7 * r7)))))));
#pragma unroll
    for (int s = 8; s > 0; s >>= 1) {
        num += __shfl_xor_sync(0xffffffffu, num, s);
        den += __shfl_xor_sync(0xffffffffu, den, s);
    }
    float g = __fdividef(num, den + 1e-10f);

    float4 oa, ob;
    oa.x = fmaf(r0, g, mn); oa.y = fmaf(r1, g, mn);
    oa.z = fmaf(r2, g, mn); oa.w = fmaf(r3, g, mn);
    ob.x = fmaf(r4, g, mn); ob.y = fmaf(r5, g, mn);
    ob.z = fmaf(r6, g, mn); ob.w = fmaf(r7, g, mn);
    out[base]      = oa;
    out[base + 16] = ob;
}

// ---------------------------------------------------------------------------
// Host: bit-faithful replication of the reference's discrete Lloyd-Max.
// CRITICAL: the linspace expression j*delta + (-10.0) must NOT fuse into an
// FMA (volatile breaks contraction), or the grid midpoint becomes +4.79e-16
// instead of exactly 0.0, the heaviest pdf point lands in the wrong bin, and
// the inner centroids shift ~9e-5 flipping the middle boundary's sign
// (the R2-R5 0.082/0.018 failures). Same for pdf*x. Capture-time only.
// ---------------------------------------------------------------------------
static void lloyd_laplace_centroids(float cf[16]) {
    static double xs[200001];
    static double pdf[200001];
    const int NX = 200001;
    const double delta = 20.0 / 200000.0;
    for (int j = 0; j < NX; j++) {
        volatile double prod = (double)j * delta;   // round the product first
        xs[j] = prod + (-10.0);                     // then round the add (no FMA)
    }
    xs[NX - 1] = 10.0;                              // numpy linspace endpoint
    for (int j = 0; j < NX; j++) pdf[j] = 0.5 * exp(-fabs(xs[j]));

    double c[16];
    for (int i = 0; i < 16; i++) {
        double p = ((double)i + 0.5) / 16.0;
        c[i] = (p < 0.5) ? log(2.0 * p) : -log(2.0 * (1.0 - p));
    }

    for (int it = 0; it < 200; it++) {
        double b[15];
        for (int i = 0; i < 15; i++) b[i] = 0.5 * (c[i + 1] + c[i]);
        double w[16], xw[16];
        for (int i = 0; i < 16; i++) { w[i] = 0.0; xw[i] = 0.0; }
        int bin = 0;  // xs ascending, boundaries ascending -> monotone advance
        for (int j = 0; j < NX; j++) {
            double x = xs[j];
            while (bin < 15 && b[bin] < x) bin++;   // searchsorted 'left'
            w[bin] += pdf[j];
            volatile double px = pdf[j] * x;        // round product (no FMA fuse)
            xw[bin] += px;
        }
        for (int i = 0; i < 16; i++) {
            if (w[i] > 0.0) c[i] = xw[i] / (w[i] > 1e-30 ? w[i] : 1e-30);
        }
    }
    for (int i = 0; i < 16; i++) cf[i] = (float)c[i];
}

extern "C" void kernel_launch(void* const* d_in, const int* in_sizes, int n_in,
                              void* d_out, int out_size) {
    (void)n_in; (void)out_size;
    const float4* in  = (const float4*)d_in[0];
    float4*       out = (float4*)d_out;

    int n     = in_sizes[0];
    int nrows = n / 128;

    // Deterministic recompute every call (no caching per harness rules).
    float cf[16];
    lloyd_laplace_centroids(cf);
    // Boundaries in f32 exactly as the reference: 0.5f * (c[i+1] + c[i])
    float bf[15];
    for (int i = 0; i < 15; i++) bf[i] = 0.5f * (cf[i + 1] + cf[i]);

    QLut lut;
    for (int k = 0; k < 7; k++) lut.c[k] = cf[7 + k];    // centroids 7..13
    for (int k = 0; k < 6; k++) lut.b[k] = bf[7 + k];    // boundaries 7..12 (b[0] ~ +4e-5)
    lut.nb6 = -(bf[13] * BIG_F);                          // exact: BIG is a power of two
    lut.nb7 = -(bf[14] * BIG_F);
    lut.d6  = cf[14] - cf[13];
    lut.d7  = cf[15] - cf[14];

    int blocks = (nrows + 15) / 16;                       // 16 rows per block
    turboquant_kernel<<<blocks, 256>>>(in, out, nrows, lut);
}